// round 10
// baseline (speedup 1.0000x reference)
#include <cuda_runtime.h>
#include <cuda_fp16.h>
#include <cuda_bf16.h>
#include <cstdint>

#define N_PTS 100000
#define KNN   16
#define NK    (N_PTS * KNN)
#define EPSB  1e-5f

// ---------------- scratch (static device memory) -----------------------------
__device__ int    g_counts[N_PTS];
__device__ float  g_y1[(size_t)N_PTS * 64];     // pre-BN layer-1 output (fp32)
__device__ __half g_z[(size_t)N_PTS * 128];     // pre-BN layer-2 output (fp16)
__device__ float  g_stats1[2 * 64];
__device__ float  g_stats2[2 * 128];
// Weight images: bf16 hi/lo planes, already in the swizzled smem-image layout.
__device__ __nv_bfloat16 g_w1img[2 * 64 * 64];   // 2 planes x 8 KB
__device__ __nv_bfloat16 g_w2img[2 * 128 * 64];  // 2 planes x 16 KB

// ---------------- helpers ------------------------------------------------------
__device__ __forceinline__ uint32_t smem_u32(const void* p) {
    uint32_t a;
    asm("{ .reg .u64 t; cvta.to.shared.u64 t, %1; cvt.u32.u64 %0, t; }"
        : "=r"(a) : "l"(p));
    return a;
}
__device__ __forceinline__ uint32_t swz(uint32_t off) {
    return off ^ ((off >> 3) & 0x70);   // 128B-row XOR swizzle, 16B granules
}
__device__ __forceinline__ void split_bf16(float v, __nv_bfloat16& hi,
                                           __nv_bfloat16& lo) {
    hi = __float2bfloat16(v);
    lo = __float2bfloat16(v - __bfloat162float(hi));
}
__device__ __forceinline__ void split2(float x, float y, uint32_t& h, uint32_t& l) {
    __nv_bfloat16 hx, lx, hy, ly;
    split_bf16(x, hx, lx);
    split_bf16(y, hy, ly);
    __nv_bfloat162 h2; h2.x = hx; h2.y = hy;
    __nv_bfloat162 l2; l2.x = lx; l2.y = ly;
    h = *(uint32_t*)&h2;
    l = *(uint32_t*)&l2;
}
__device__ __forceinline__ void ldsm_x4(uint32_t* r, uint32_t addr) {
    asm volatile(
        "ldmatrix.sync.aligned.m8n8.x4.shared.b16 {%0,%1,%2,%3}, [%4];"
        : "=r"(r[0]), "=r"(r[1]), "=r"(r[2]), "=r"(r[3]) : "r"(addr));
}
__device__ __forceinline__ void mma_bf16(float* c, const uint32_t* a,
                                         const uint32_t* b) {
    asm volatile(
        "mma.sync.aligned.m16n8k16.row.col.f32.bf16.bf16.f32 "
        "{%0,%1,%2,%3}, {%4,%5,%6,%7}, {%8,%9}, {%0,%1,%2,%3};"
        : "+f"(c[0]), "+f"(c[1]), "+f"(c[2]), "+f"(c[3])
        : "r"(a[0]), "r"(a[1]), "r"(a[2]), "r"(a[3]), "r"(b[0]), "r"(b[1]));
}
__device__ __forceinline__ float warp_sum8(float v) {
    v += __shfl_xor_sync(0xffffffffu, v, 4);
    v += __shfl_xor_sync(0xffffffffu, v, 8);
    v += __shfl_xor_sync(0xffffffffu, v, 16);
    return v;
}

// ---------------- zero + weight-image pack --------------------------------------
__global__ void zero_pack_kernel(const float* __restrict__ W1,
                                 const float* __restrict__ W2) {
    int i = blockIdx.x * blockDim.x + threadIdx.x;
    if (i < N_PTS) g_counts[i] = 0;
    if (i < 2 * 64) g_stats1[i] = 0.f;
    if (i < 2 * 128) g_stats2[i] = 0.f;
    if (i < 4096) {                       // W1: Bt[n][k] = W1[k][n]
        int k = i & 63, n = i >> 6;
        __nv_bfloat16 h, l;
        split_bf16(W1[k * 64 + n], h, l);
        uint32_t off = swz((uint32_t)(n * 128 + k * 2));
        *(__nv_bfloat16*)((char*)g_w1img + off) = h;
        *(__nv_bfloat16*)((char*)g_w1img + 8192 + off) = l;
    }
    if (i < 8192) {                       // W2: Bt[n][k] = W2[k][n]
        int k = i & 63, n = i >> 6;
        __nv_bfloat16 h, l;
        split_bf16(W2[k * 128 + n], h, l);
        uint32_t off = swz((uint32_t)(n * 128 + k * 2));
        *(__nv_bfloat16*)((char*)g_w2img + off) = h;
        *(__nv_bfloat16*)((char*)g_w2img + 16384 + off) = l;
    }
}

__global__ void count_kernel(const int4* __restrict__ idx4) {
    int i = blockIdx.x * blockDim.x + threadIdx.x;
    if (i < NK / 4) {
        int4 v = idx4[i];
        atomicAdd(&g_counts[v.x], 1);
        atomicAdd(&g_counts[v.y], 1);
        atomicAdd(&g_counts[v.z], 1);
        atomicAdd(&g_counts[v.w], 1);
    }
}

// ---------------- GEMM1 (HMMA): y1 = feat @ W1 + b1, weighted BN1 stats -------
// CTA: 128 rows x 64 cols, 512 threads = 16 warps as 8(row)x2(col); warp 16x32.
#define G1_AHI 0u
#define G1_ALO 16384u
#define G1_B   32768u        // BHI (8KB) + BLO (8KB) contiguous
#define G1_SMEM (49152 + 1024)

__global__ __launch_bounds__(512) void gemm1_mma(const float* __restrict__ feat,
                                                 const float* __restrict__ b1) {
    extern __shared__ char dsm[];
    uint32_t raw = smem_u32(dsm);
    uint32_t sbase = (raw + 1023u) & ~1023u;
    char* smp = dsm + (sbase - raw);
    const int tid = threadIdx.x;
    const int wi = tid >> 5, lane = tid & 31;
    const int row0 = blockIdx.x * 128;

    // B: straight 16 KB copy of the pre-swizzled image (hi plane then lo plane)
#pragma unroll
    for (int f = tid; f < 1024; f += 512)
        ((uint4*)(smp + G1_B))[f] = ((const uint4*)g_w1img)[f];
    // A: 16-byte granules; thread -> one row x 8 cols, hi+lo uint4 stores
#pragma unroll
    for (int f = tid; f < 1024; f += 512) {
        int r = f >> 3, g8 = f & 7;
        float4 v0 = make_float4(0.f, 0.f, 0.f, 0.f), v1 = v0;
        if (row0 + r < N_PTS) {
            const float4* src = (const float4*)&feat[(size_t)(row0 + r) * 64 + g8 * 8];
            v0 = src[0];
            v1 = src[1];
        }
        uint4 h4, l4;
        split2(v0.x, v0.y, h4.x, l4.x);
        split2(v0.z, v0.w, h4.y, l4.y);
        split2(v1.x, v1.y, h4.z, l4.z);
        split2(v1.z, v1.w, h4.w, l4.w);
        uint32_t sw = swz((uint32_t)(r * 128 + g8 * 16));
        *(uint4*)(smp + G1_AHI + sw) = h4;
        *(uint4*)(smp + G1_ALO + sw) = l4;
    }
    __syncthreads();

    const int mrow0 = (wi >> 1) * 16;
    const int ncol0 = (wi & 1) * 32;

    float acc[4][4];
#pragma unroll
    for (int n = 0; n < 4; n++)
#pragma unroll
        for (int q = 0; q < 4; q++) acc[n][q] = 0.f;

#pragma unroll
    for (int ks = 0; ks < 4; ks++) {
        const uint32_t kb = (uint32_t)(ks * 32);
        uint32_t aH[4], aL[4], bH[2][4], bL[2][4];
        uint32_t swa = swz((uint32_t)((mrow0 + (lane & 15)) * 128) + kb +
                           (uint32_t)((lane >> 4) * 16));
        ldsm_x4(aH, sbase + G1_AHI + swa);
        ldsm_x4(aL, sbase + G1_ALO + swa);
#pragma unroll
        for (int np = 0; np < 2; np++) {
            uint32_t swb = swz((uint32_t)((ncol0 + np * 16 + ((lane >> 4) << 3) +
                                           (lane & 7)) * 128) + kb +
                               (uint32_t)(((lane >> 3) & 1) * 16));
            ldsm_x4(bH[np], sbase + G1_B + swb);
            ldsm_x4(bL[np], sbase + G1_B + 8192u + swb);
        }
#pragma unroll
        for (int n = 0; n < 4; n++) {
            const uint32_t* bh = &bH[n >> 1][(n & 1) * 2];
            const uint32_t* bl = &bL[n >> 1][(n & 1) * 2];
            mma_bf16(acc[n], aH, bh);
            mma_bf16(acc[n], aH, bl);
            mma_bf16(acc[n], aL, bh);
        }
    }

    const int g = lane >> 2, t = lane & 3;
    int r0 = row0 + mrow0 + g;
    int r1 = r0 + 8;
    bool v0 = r0 < N_PTS, v1 = r1 < N_PTS;
    float w0 = v0 ? (float)g_counts[r0] : 0.f;
    float w1 = v1 ? (float)g_counts[r1] : 0.f;
    float ps[4][2], qs[4][2];
#pragma unroll
    for (int n = 0; n < 4; n++) {
        int col = ncol0 + n * 8 + t * 2;
        float bc0 = b1[col], bc1 = b1[col + 1];
        float y00 = acc[n][0] + bc0, y01 = acc[n][1] + bc1;
        float y10 = acc[n][2] + bc0, y11 = acc[n][3] + bc1;
        if (v0) *(float2*)&g_y1[(size_t)r0 * 64 + col] = make_float2(y00, y01);
        if (v1) *(float2*)&g_y1[(size_t)r1 * 64 + col] = make_float2(y10, y11);
        ps[n][0] = w0 * y00 + w1 * y10;
        ps[n][1] = w0 * y01 + w1 * y11;
        qs[n][0] = w0 * y00 * y00 + w1 * y10 * y10;
        qs[n][1] = w0 * y01 * y01 + w1 * y11 * y11;
    }
#pragma unroll
    for (int n = 0; n < 4; n++) {
        float s0 = warp_sum8(ps[n][0]);
        float s1 = warp_sum8(ps[n][1]);
        float q0 = warp_sum8(qs[n][0]);
        float q1 = warp_sum8(qs[n][1]);
        if (lane < 4) {
            int col = ncol0 + n * 8 + lane * 2;
            atomicAdd(&g_stats1[col], s0);
            atomicAdd(&g_stats1[col + 1], s1);
            atomicAdd(&g_stats1[64 + col], q0);
            atomicAdd(&g_stats1[64 + col + 1], q1);
        }
    }
}

// ---------------- GEMM2 (HMMA): h=relu(bn1(y1)); y2=h@W2+b2 -> fp16 + stats ---
// CTA: 128 rows x 128 cols, 512 threads = 16 warps as 4(row)x4(col); warp 32x32.
#define G2_AHI 0u
#define G2_ALO 16384u
#define G2_B   32768u        // BHI (16KB) + BLO (16KB) contiguous
#define G2_SB1 65536u        // scale[64] + bias[64]
#define G2_SMEM (66048 + 1024)

__global__ __launch_bounds__(512) void gemm2_mma(const float* __restrict__ b2,
                                                 const float* __restrict__ gamma1,
                                                 const float* __restrict__ beta1) {
    extern __shared__ char dsm[];
    uint32_t raw = smem_u32(dsm);
    uint32_t sbase = (raw + 1023u) & ~1023u;
    char* smp = dsm + (sbase - raw);
    const int tid = threadIdx.x;
    const int wi = tid >> 5, lane = tid & 31;
    const int row0 = blockIdx.x * 128;

    if (tid < 64) {
        const float inv_m = 1.0f / (float)NK;
        float mean = g_stats1[tid] * inv_m;
        float var = g_stats1[64 + tid] * inv_m - mean * mean;
        float sc = gamma1[tid] * rsqrtf(var + EPSB);
        *(float*)(smp + G2_SB1 + tid * 4) = sc;
        *(float*)(smp + G2_SB1 + 256 + tid * 4) = beta1[tid] - mean * sc;
    }
    // B: straight 32 KB copy of the pre-swizzled image
#pragma unroll
    for (int f = tid; f < 2048; f += 512)
        ((uint4*)(smp + G2_B))[f] = ((const uint4*)g_w2img)[f];
    __syncthreads();   // sb1 ready for A construction

    // A: h = relu(bn1(y1)), 16-byte granules
#pragma unroll
    for (int f = tid; f < 1024; f += 512) {
        int r = f >> 3, g8 = f & 7;
        float4 v0 = make_float4(0.f, 0.f, 0.f, 0.f), v1 = v0;
        if (row0 + r < N_PTS) {
            const float4* src = (const float4*)&g_y1[(size_t)(row0 + r) * 64 + g8 * 8];
            v0 = src[0];
            v1 = src[1];
        }
        float4 s0 = *(const float4*)(smp + G2_SB1 + g8 * 32);
        float4 s1 = *(const float4*)(smp + G2_SB1 + g8 * 32 + 16);
        float4 i0 = *(const float4*)(smp + G2_SB1 + 256 + g8 * 32);
        float4 i1 = *(const float4*)(smp + G2_SB1 + 256 + g8 * 32 + 16);
        v0.x = fmaxf(fmaf(v0.x, s0.x, i0.x), 0.f);
        v0.y = fmaxf(fmaf(v0.y, s0.y, i0.y), 0.f);
        v0.z = fmaxf(fmaf(v0.z, s0.z, i0.z), 0.f);
        v0.w = fmaxf(fmaf(v0.w, s0.w, i0.w), 0.f);
        v1.x = fmaxf(fmaf(v1.x, s1.x, i1.x), 0.f);
        v1.y = fmaxf(fmaf(v1.y, s1.y, i1.y), 0.f);
        v1.z = fmaxf(fmaf(v1.z, s1.z, i1.z), 0.f);
        v1.w = fmaxf(fmaf(v1.w, s1.w, i1.w), 0.f);
        uint4 h4, l4;
        split2(v0.x, v0.y, h4.x, l4.x);
        split2(v0.z, v0.w, h4.y, l4.y);
        split2(v1.x, v1.y, h4.z, l4.z);
        split2(v1.z, v1.w, h4.w, l4.w);
        uint32_t sw = swz((uint32_t)(r * 128 + g8 * 16));
        *(uint4*)(smp + G2_AHI + sw) = h4;
        *(uint4*)(smp + G2_ALO + sw) = l4;
    }
    __syncthreads();

    const int mrow0 = (wi >> 2) * 32;
    const int ncol0 = (wi & 3) * 32;

    float acc[2][4][4];
#pragma unroll
    for (int m = 0; m < 2; m++)
#pragma unroll
        for (int n = 0; n < 4; n++)
#pragma unroll
            for (int q = 0; q < 4; q++) acc[m][n][q] = 0.f;

#pragma unroll
    for (int ks = 0; ks < 4; ks++) {
        const uint32_t kb = (uint32_t)(ks * 32);
        uint32_t aH[2][4], aL[2][4], bH[2][4], bL[2][4];
#pragma unroll
        for (int m = 0; m < 2; m++) {
            uint32_t swa = swz((uint32_t)((mrow0 + m * 16 + (lane & 15)) * 128) + kb +
                               (uint32_t)((lane >> 4) * 16));
            ldsm_x4(aH[m], sbase + G2_AHI + swa);
            ldsm_x4(aL[m], sbase + G2_ALO + swa);
        }
#pragma unroll
        for (int np = 0; np < 2; np++) {
            uint32_t swb = swz((uint32_t)((ncol0 + np * 16 + ((lane >> 4) << 3) +
                                           (lane & 7)) * 128) + kb +
                               (uint32_t)(((lane >> 3) & 1) * 16));
            ldsm_x4(bH[np], sbase + G2_B + swb);
            ldsm_x4(bL[np], sbase + G2_B + 16384u + swb);
        }
#pragma unroll
        for (int m = 0; m < 2; m++)
#pragma unroll
            for (int n = 0; n < 4; n++) {
                const uint32_t* bh = &bH[n >> 1][(n & 1) * 2];
                const uint32_t* bl = &bL[n >> 1][(n & 1) * 2];
                mma_bf16(acc[m][n], aH[m], bh);
                mma_bf16(acc[m][n], aH[m], bl);
                mma_bf16(acc[m][n], aL[m], bh);
            }
    }

    const int g = lane >> 2, t = lane & 3;
    float ps[4][2], qs[4][2];
#pragma unroll
    for (int n = 0; n < 4; n++) { ps[n][0] = ps[n][1] = qs[n][0] = qs[n][1] = 0.f; }
#pragma unroll
    for (int m = 0; m < 2; m++) {
        int r0 = row0 + mrow0 + m * 16 + g;
        int r1 = r0 + 8;
        bool v0 = r0 < N_PTS, v1 = r1 < N_PTS;
        float w0 = v0 ? (float)g_counts[r0] : 0.f;
        float w1 = v1 ? (float)g_counts[r1] : 0.f;
#pragma unroll
        for (int n = 0; n < 4; n++) {
            int col = ncol0 + n * 8 + t * 2;
            float bc0 = b2[col], bc1 = b2[col + 1];
            float y00 = acc[m][n][0] + bc0, y01 = acc[m][n][1] + bc1;
            float y10 = acc[m][n][2] + bc0, y11 = acc[m][n][3] + bc1;
            if (v0) *(__half2*)&g_z[(size_t)r0 * 128 + col] = __floats2half2_rn(y00, y01);
            if (v1) *(__half2*)&g_z[(size_t)r1 * 128 + col] = __floats2half2_rn(y10, y11);
            ps[n][0] += w0 * y00 + w1 * y10;
            ps[n][1] += w0 * y01 + w1 * y11;
            qs[n][0] += w0 * y00 * y00 + w1 * y10 * y10;
            qs[n][1] += w0 * y01 * y01 + w1 * y11 * y11;
        }
    }
#pragma unroll
    for (int n = 0; n < 4; n++) {
        float s0 = warp_sum8(ps[n][0]);
        float s1 = warp_sum8(ps[n][1]);
        float q0 = warp_sum8(qs[n][0]);
        float q1 = warp_sum8(qs[n][1]);
        if (lane < 4) {
            int col = ncol0 + n * 8 + lane * 2;
            atomicAdd(&g_stats2[col], s0);
            atomicAdd(&g_stats2[col + 1], s1);
            atomicAdd(&g_stats2[128 + col], q0);
            atomicAdd(&g_stats2[128 + col + 1], q1);
        }
    }
}

// ---------------- gather + max/min pool + folded BN2 + ReLU -------------------
__global__ __launch_bounds__(256) void gather_max_kernel(
    const int* __restrict__ idx, const float* __restrict__ gamma2,
    const float* __restrict__ beta2, float* __restrict__ out) {
    int warp = (blockIdx.x * blockDim.x + threadIdx.x) >> 5;
    int lane = threadIdx.x & 31;
    int p = warp * 2 + (lane >> 4);
    if (p >= N_PTS) return;
    int half_lane = lane & 15;
    int c0 = half_lane * 8;

    int myidx = idx[p * 16 + half_lane];

    __half2 mx[4], mn[4];
#pragma unroll
    for (int j = 0; j < 4; j++) {
        mx[j] = __floats2half2_rn(-65504.f, -65504.f);
        mn[j] = __floats2half2_rn(65504.f, 65504.f);
    }

#pragma unroll
    for (int k = 0; k < 16; k++) {
        int r = __shfl_sync(0xffffffffu, myidx, (lane & 16) + k);
        uint4 rawv = *(const uint4*)&g_z[(size_t)r * 128 + c0];
        __half2 v[4];
        *(uint4*)v = rawv;
        mx[0] = __hmax2(mx[0], v[0]); mn[0] = __hmin2(mn[0], v[0]);
        mx[1] = __hmax2(mx[1], v[1]); mn[1] = __hmin2(mn[1], v[1]);
        mx[2] = __hmax2(mx[2], v[2]); mn[2] = __hmin2(mn[2], v[2]);
        mx[3] = __hmax2(mx[3], v[3]); mn[3] = __hmin2(mn[3], v[3]);
    }

    const float inv_m = 1.0f / (float)NK;
    float4 sum0 = *(const float4*)&g_stats2[c0];
    float4 sum1 = *(const float4*)&g_stats2[c0 + 4];
    float4 sq0 = *(const float4*)&g_stats2[128 + c0];
    float4 sq1 = *(const float4*)&g_stats2[128 + c0 + 4];
    float4 gm0 = *(const float4*)&gamma2[c0];
    float4 gm1 = *(const float4*)&gamma2[c0 + 4];
    float4 bt0 = *(const float4*)&beta2[c0];
    float4 bt1 = *(const float4*)&beta2[c0 + 4];
    float sm[8] = {sum0.x, sum0.y, sum0.z, sum0.w, sum1.x, sum1.y, sum1.z, sum1.w};
    float sq[8] = {sq0.x, sq0.y, sq0.z, sq0.w, sq1.x, sq1.y, sq1.z, sq1.w};
    float gm[8] = {gm0.x, gm0.y, gm0.z, gm0.w, gm1.x, gm1.y, gm1.z, gm1.w};
    float bt[8] = {bt0.x, bt0.y, bt0.z, bt0.w, bt1.x, bt1.y, bt1.z, bt1.w};

    float o[8];
#pragma unroll
    for (int j = 0; j < 8; j++) {
        float mean = sm[j] * inv_m;
        float var = sq[j] * inv_m - mean * mean;
        float sc = gm[j] * rsqrtf(var + EPSB);
        float bi = bt[j] - mean * sc;
        float2 fx = __half22float2(mx[j >> 1]);
        float2 fn = __half22float2(mn[j >> 1]);
        float vx = (j & 1) ? fx.y : fx.x;
        float vn = (j & 1) ? fn.y : fn.x;
        float m = (sc >= 0.f) ? vx : vn;
        o[j] = fmaxf(fmaf(sc, m, bi), 0.f);
    }
    size_t off = (size_t)p * 128 + c0;
    *(float4*)&out[off]     = make_float4(o[0], o[1], o[2], o[3]);
    *(float4*)&out[off + 4] = make_float4(o[4], o[5], o[6], o[7]);
}

// ---------------- launch --------------------------------------------------------
extern "C" void kernel_launch(void* const* d_in, const int* in_sizes, int n_in,
                              void* d_out, int out_size) {
    const float* feat = (const float*)d_in[0];
    const int* idx = (const int*)d_in[1];
    const float* W1 = (const float*)d_in[2];
    const float* b1 = (const float*)d_in[3];
    const float* g1 = (const float*)d_in[4];
    const float* be1 = (const float*)d_in[5];
    const float* W2 = (const float*)d_in[6];
    const float* b2 = (const float*)d_in[7];
    const float* g2 = (const float*)d_in[8];
    const float* be2 = (const float*)d_in[9];
    float* out = (float*)d_out;

    cudaFuncSetAttribute(gemm1_mma, cudaFuncAttributeMaxDynamicSharedMemorySize, G1_SMEM);
    cudaFuncSetAttribute(gemm2_mma, cudaFuncAttributeMaxDynamicSharedMemorySize, G2_SMEM);

    zero_pack_kernel<<<(N_PTS + 255) / 256, 256>>>(W1, W2);
    count_kernel<<<(NK / 4 + 255) / 256, 256>>>((const int4*)idx);
    gemm1_mma<<<(N_PTS + 127) / 128, 512, G1_SMEM>>>(feat, b1);
    gemm2_mma<<<(N_PTS + 127) / 128, 512, G2_SMEM>>>(b2, g1, be1);
    gather_max_kernel<<<(N_PTS * 16 + 255) / 256, 256>>>(idx, g2, be2, out);
}

// round 11
// speedup vs baseline: 1.7516x; 1.7516x over previous
#include <cuda_runtime.h>
#include <cuda_fp16.h>
#include <cstdint>

#define N_PTS 100000
#define KNN   16
#define NK    (N_PTS * KNN)
#define EPSB  1e-5f
#define ASTRIDE 68   // padded A row stride (floats) -> conflict-free broadcasts

// ---------------- scratch (static device memory; no dynamic alloc) ----------
__device__ int    g_counts[N_PTS];
__device__ float  g_y1[(size_t)N_PTS * 64];    // pre-BN layer-1 output (fp32)
__device__ __half g_z[(size_t)N_PTS * 128];    // pre-BN layer-2 output (fp16)
__device__ float  g_stats1[2 * 64];            // weighted sum, sumsq
__device__ float  g_stats2[2 * 128];

// ---------------- packed f32x2 helpers --------------------------------------
__device__ __forceinline__ unsigned long long pack2s(float a) {
    unsigned long long r;
    asm("mov.b64 %0, {%1, %1};" : "=l"(r) : "f"(a));
    return r;
}
__device__ __forceinline__ float2 unpack2(unsigned long long v) {
    float2 r;
    asm("mov.b64 {%0, %1}, %2;" : "=f"(r.x), "=f"(r.y) : "l"(v));
    return r;
}
__device__ __forceinline__ void fma2(unsigned long long& d,
                                     unsigned long long a,
                                     unsigned long long b) {
    asm("fma.rn.f32x2 %0, %1, %2, %0;" : "+l"(d) : "l"(a), "l"(b));
}

// ---------------- small kernels ----------------------------------------------
__global__ void zero_kernel() {
    int i = blockIdx.x * blockDim.x + threadIdx.x;
    if (i < N_PTS) g_counts[i] = 0;
    if (i < 2 * 64) g_stats1[i] = 0.f;
    if (i < 2 * 128) g_stats2[i] = 0.f;
}

__global__ void count_kernel(const int4* __restrict__ idx4) {
    int i = blockIdx.x * blockDim.x + threadIdx.x;
    if (i < NK / 4) {
        int4 v = idx4[i];
        atomicAdd(&g_counts[v.x], 1);
        atomicAdd(&g_counts[v.y], 1);
        atomicAdd(&g_counts[v.z], 1);
        atomicAdd(&g_counts[v.w], 1);
    }
}

// GEMM1: y1 = feat @ W1 + b1 ; weighted BN1 stats.
// Block: 128 rows x 64 cols, 256 threads as 8(tx) x 32(ty).
// Thread tile: 4 rows x 8 cols ({tx*4..+3, 32+tx*4..+3}).  (R7-verbatim)
__global__ __launch_bounds__(256, 3) void gemm1_kernel(const float* __restrict__ feat,
                                                       const float* __restrict__ W1,
                                                       const float* __restrict__ b1) {
    __shared__ float As[128 * ASTRIDE];  // ~34 KB, [row][k] padded
    __shared__ float Bs[64 * 64];        // 16 KB, [k][col]
    const int tid = threadIdx.x;
    const int tx = tid & 7, ty = tid >> 3;
    const int row0 = blockIdx.x * 128;

#pragma unroll
    for (int it = 0; it < 4; it++) {
        int f = tid + it * 256;
        ((float4*)Bs)[f] = ((const float4*)W1)[f];
    }
#pragma unroll
    for (int it = 0; it < 8; it++) {
        int f = tid + it * 256;          // [0, 2048)
        int r = f >> 4, k4 = f & 15;
        int grow = row0 + r;
        float4 v = (grow < N_PTS) ? ((const float4*)feat)[grow * 16 + k4]
                                  : make_float4(0.f, 0.f, 0.f, 0.f);
        *(float4*)&As[r * ASTRIDE + k4 * 4] = v;
    }
    __syncthreads();

    unsigned long long acc[4][4];
#pragma unroll
    for (int i = 0; i < 4; i++)
#pragma unroll
        for (int j = 0; j < 4; j++) acc[i][j] = 0ull;

#pragma unroll
    for (int kk = 0; kk < 64; kk += 2) {
        float2 a[4];
#pragma unroll
        for (int i = 0; i < 4; i++)
            a[i] = *(const float2*)&As[(ty * 4 + i) * ASTRIDE + kk];
#pragma unroll
        for (int kq = 0; kq < 2; kq++) {
            const ulonglong2 bA = *(const ulonglong2*)&Bs[(kk + kq) * 64 + tx * 4];
            const ulonglong2 bB = *(const ulonglong2*)&Bs[(kk + kq) * 64 + 32 + tx * 4];
#pragma unroll
            for (int i = 0; i < 4; i++) {
                unsigned long long ad = pack2s(kq ? a[i].y : a[i].x);
                fma2(acc[i][0], ad, bA.x);
                fma2(acc[i][1], ad, bA.y);
                fma2(acc[i][2], ad, bB.x);
                fma2(acc[i][3], ad, bB.y);
            }
        }
    }

    const float4 biasA = *(const float4*)&b1[tx * 4];
    const float4 biasB = *(const float4*)&b1[32 + tx * 4];
    float ws[8], wq[8];
#pragma unroll
    for (int j = 0; j < 8; j++) { ws[j] = 0.f; wq[j] = 0.f; }
#pragma unroll
    for (int i = 0; i < 4; i++) {
        int grow = row0 + ty * 4 + i;
        if (grow >= N_PTS) continue;
        float2 p0 = unpack2(acc[i][0]);
        float2 p1 = unpack2(acc[i][1]);
        float2 p2 = unpack2(acc[i][2]);
        float2 p3 = unpack2(acc[i][3]);
        float y[8];
        y[0] = p0.x + biasA.x; y[1] = p0.y + biasA.y;
        y[2] = p1.x + biasA.z; y[3] = p1.y + biasA.w;
        y[4] = p2.x + biasB.x; y[5] = p2.y + biasB.y;
        y[6] = p3.x + biasB.z; y[7] = p3.y + biasB.w;
        *(float4*)&g_y1[(size_t)grow * 64 + tx * 4] = make_float4(y[0], y[1], y[2], y[3]);
        *(float4*)&g_y1[(size_t)grow * 64 + 32 + tx * 4] = make_float4(y[4], y[5], y[6], y[7]);
        float w = (float)g_counts[grow];
#pragma unroll
        for (int j = 0; j < 8; j++) {
            ws[j] += w * y[j];
            wq[j] += w * y[j] * y[j];
        }
    }
    __syncthreads();
    float* red = As;  // 8704 floats available, need 2 * 2048
#pragma unroll
    for (int j = 0; j < 4; j++) {
        red[ty * 64 + tx * 4 + j] = ws[j];
        red[ty * 64 + 32 + tx * 4 + j] = ws[4 + j];
        red[2048 + ty * 64 + tx * 4 + j] = wq[j];
        red[2048 + ty * 64 + 32 + tx * 4 + j] = wq[4 + j];
    }
    __syncthreads();
    if (tid < 64) {
        float s = 0.f, q = 0.f;
#pragma unroll
        for (int t = 0; t < 32; t++) {
            s += red[t * 64 + tid];
            q += red[2048 + t * 64 + tid];
        }
        atomicAdd(&g_stats1[tid], s);
        atomicAdd(&g_stats1[64 + tid], q);
    }
}

// GEMM2: h = relu(bn1(y1)); y2 = h @ W2 + b2 -> fp16 g_z; weighted BN2 stats.
// Block: 128 rows x 64 cols (blockIdx.y = N-half), 256 threads as 16(tx) x 16(ty).
// Thread tile: 8 rows ({ty*4+i, 64+ty*4+i}) x 4 cols (tx*4..+3).
// Smaller acc (16 regs) -> 3 CTAs/SM = 24 warps for latency hiding.
__global__ __launch_bounds__(256, 3) void gemm2_kernel(const float* __restrict__ W2,
                                                       const float* __restrict__ b2,
                                                       const float* __restrict__ gamma1,
                                                       const float* __restrict__ beta1) {
    __shared__ float As[128 * ASTRIDE];  // ~34 KB, [row][k] padded
    __shared__ float Bs[64 * 64];        // 16 KB, [k][col-half]
    __shared__ float sb1s[128];
    const int tid = threadIdx.x;
    const int tx = tid & 15, ty = tid >> 4;
    const int row0 = blockIdx.x * 128;
    const int col0 = blockIdx.y * 64;

    if (tid < 64) {
        const float inv_m = 1.0f / (float)NK;
        float mean = g_stats1[tid] * inv_m;
        float var = g_stats1[64 + tid] * inv_m - mean * mean;
        float sc = gamma1[tid] * rsqrtf(var + EPSB);
        sb1s[tid] = sc;
        sb1s[64 + tid] = beta1[tid] - mean * sc;
    }
    // B half: Bs[k][0..63] = W2[k][col0..col0+63]
#pragma unroll
    for (int it = 0; it < 4; it++) {
        int f = tid + it * 256;           // [0, 1024): k = f>>4, c4 = f&15
        int k = f >> 4, c4 = f & 15;
        ((float4*)Bs)[f] = *(const float4*)&W2[k * 128 + col0 + c4 * 4];
    }
    __syncthreads();   // sb1s ready

#pragma unroll
    for (int it = 0; it < 8; it++) {
        int f = tid + it * 256;          // [0, 2048)
        int r = f >> 4, k4 = f & 15;
        int grow = row0 + r;
        float4 v = (grow < N_PTS) ? ((const float4*)g_y1)[grow * 16 + k4]
                                  : make_float4(0.f, 0.f, 0.f, 0.f);
        float4 s = *(const float4*)&sb1s[k4 * 4];
        float4 bb = *(const float4*)&sb1s[64 + k4 * 4];
        v.x = fmaxf(fmaf(v.x, s.x, bb.x), 0.f);
        v.y = fmaxf(fmaf(v.y, s.y, bb.y), 0.f);
        v.z = fmaxf(fmaf(v.z, s.z, bb.z), 0.f);
        v.w = fmaxf(fmaf(v.w, s.w, bb.w), 0.f);
        *(float4*)&As[r * ASTRIDE + k4 * 4] = v;
    }
    __syncthreads();

    unsigned long long acc[8][2];
#pragma unroll
    for (int i = 0; i < 8; i++) { acc[i][0] = 0ull; acc[i][1] = 0ull; }

#pragma unroll
    for (int kk = 0; kk < 64; kk += 2) {
        float2 a[8];
#pragma unroll
        for (int i = 0; i < 4; i++) {
            a[i]     = *(const float2*)&As[(ty * 4 + i) * ASTRIDE + kk];
            a[4 + i] = *(const float2*)&As[(64 + ty * 4 + i) * ASTRIDE + kk];
        }
#pragma unroll
        for (int kq = 0; kq < 2; kq++) {
            const ulonglong2 bA = *(const ulonglong2*)&Bs[(kk + kq) * 64 + tx * 4];
#pragma unroll
            for (int i = 0; i < 8; i++) {
                unsigned long long ad = pack2s(kq ? a[i].y : a[i].x);
                fma2(acc[i][0], ad, bA.x);
                fma2(acc[i][1], ad, bA.y);
            }
        }
    }

    const float4 biasA = *(const float4*)&b2[col0 + tx * 4];
    float ws[4] = {0.f, 0.f, 0.f, 0.f}, wq[4] = {0.f, 0.f, 0.f, 0.f};
#pragma unroll
    for (int i = 0; i < 8; i++) {
        int grow = row0 + ((i < 4) ? (ty * 4 + i) : (64 + ty * 4 + (i - 4)));
        if (grow >= N_PTS) continue;
        float2 p0 = unpack2(acc[i][0]);
        float2 p1 = unpack2(acc[i][1]);
        float y0 = p0.x + biasA.x, y1v = p0.y + biasA.y;
        float y2v = p1.x + biasA.z, y3 = p1.y + biasA.w;
        __half2 h0 = __floats2half2_rn(y0, y1v);
        __half2 h1 = __floats2half2_rn(y2v, y3);
        uint2 hv;
        hv.x = *(uint32_t*)&h0;
        hv.y = *(uint32_t*)&h1;
        *(uint2*)&g_z[(size_t)grow * 128 + col0 + tx * 4] = hv;
        float w = (float)g_counts[grow];
        ws[0] += w * y0;  wq[0] += w * y0 * y0;
        ws[1] += w * y1v; wq[1] += w * y1v * y1v;
        ws[2] += w * y2v; wq[2] += w * y2v * y2v;
        ws[3] += w * y3;  wq[3] += w * y3 * y3;
    }
    __syncthreads();
    float* red = As;  // need 2 * 1024 floats
#pragma unroll
    for (int j = 0; j < 4; j++) {
        red[ty * 64 + tx * 4 + j] = ws[j];
        red[1024 + ty * 64 + tx * 4 + j] = wq[j];
    }
    __syncthreads();
    if (tid < 64) {
        float s = 0.f, q = 0.f;
#pragma unroll
        for (int t = 0; t < 16; t++) {
            s += red[t * 64 + tid];
            q += red[1024 + t * 64 + tid];
        }
        atomicAdd(&g_stats2[col0 + tid], s);
        atomicAdd(&g_stats2[128 + col0 + tid], q);
    }
}

// Final gather + max/min-pool over pre-BN fp16 table, then folded BN2
// affine + ReLU (per-thread from g_stats2). One warp = TWO points.
__global__ __launch_bounds__(256) void gather_max_kernel(
    const int* __restrict__ idx, const float* __restrict__ gamma2,
    const float* __restrict__ beta2, float* __restrict__ out) {
    int warp = (blockIdx.x * blockDim.x + threadIdx.x) >> 5;
    int lane = threadIdx.x & 31;
    int p = warp * 2 + (lane >> 4);
    if (p >= N_PTS) return;
    int half_lane = lane & 15;
    int c0 = half_lane * 8;

    int myidx = idx[p * 16 + half_lane];

    __half2 mx[4], mn[4];
#pragma unroll
    for (int j = 0; j < 4; j++) {
        mx[j] = __floats2half2_rn(-65504.f, -65504.f);
        mn[j] = __floats2half2_rn(65504.f, 65504.f);
    }

#pragma unroll
    for (int k = 0; k < 16; k++) {
        int r = __shfl_sync(0xffffffffu, myidx, (lane & 16) + k);
        uint4 raw = *(const uint4*)&g_z[(size_t)r * 128 + c0];
        __half2 v[4];
        *(uint4*)v = raw;
        mx[0] = __hmax2(mx[0], v[0]); mn[0] = __hmin2(mn[0], v[0]);
        mx[1] = __hmax2(mx[1], v[1]); mn[1] = __hmin2(mn[1], v[1]);
        mx[2] = __hmax2(mx[2], v[2]); mn[2] = __hmin2(mn[2], v[2]);
        mx[3] = __hmax2(mx[3], v[3]); mn[3] = __hmin2(mn[3], v[3]);
    }

    const float inv_m = 1.0f / (float)NK;
    float4 sum0 = *(const float4*)&g_stats2[c0];
    float4 sum1 = *(const float4*)&g_stats2[c0 + 4];
    float4 sq0 = *(const float4*)&g_stats2[128 + c0];
    float4 sq1 = *(const float4*)&g_stats2[128 + c0 + 4];
    float4 gm0 = *(const float4*)&gamma2[c0];
    float4 gm1 = *(const float4*)&gamma2[c0 + 4];
    float4 bt0 = *(const float4*)&beta2[c0];
    float4 bt1 = *(const float4*)&beta2[c0 + 4];
    float sm[8] = {sum0.x, sum0.y, sum0.z, sum0.w, sum1.x, sum1.y, sum1.z, sum1.w};
    float sq[8] = {sq0.x, sq0.y, sq0.z, sq0.w, sq1.x, sq1.y, sq1.z, sq1.w};
    float gm[8] = {gm0.x, gm0.y, gm0.z, gm0.w, gm1.x, gm1.y, gm1.z, gm1.w};
    float bt[8] = {bt0.x, bt0.y, bt0.z, bt0.w, bt1.x, bt1.y, bt1.z, bt1.w};

    float o[8];
#pragma unroll
    for (int j = 0; j < 8; j++) {
        float mean = sm[j] * inv_m;
        float var = sq[j] * inv_m - mean * mean;
        float sc = gm[j] * rsqrtf(var + EPSB);
        float bi = bt[j] - mean * sc;
        float2 fx = __half22float2(mx[j >> 1]);
        float2 fn = __half22float2(mn[j >> 1]);
        float vx = (j & 1) ? fx.y : fx.x;
        float vn = (j & 1) ? fn.y : fn.x;
        float m = (sc >= 0.f) ? vx : vn;
        o[j] = fmaxf(fmaf(sc, m, bi), 0.f);
    }
    size_t off = (size_t)p * 128 + c0;
    *(float4*)&out[off]     = make_float4(o[0], o[1], o[2], o[3]);
    *(float4*)&out[off + 4] = make_float4(o[4], o[5], o[6], o[7]);
}

// ---------------- launch ------------------------------------------------------
extern "C" void kernel_launch(void* const* d_in, const int* in_sizes, int n_in,
                              void* d_out, int out_size) {
    const float* feat = (const float*)d_in[0];
    const int* idx = (const int*)d_in[1];
    const float* W1 = (const float*)d_in[2];
    const float* b1 = (const float*)d_in[3];
    const float* g1 = (const float*)d_in[4];
    const float* be1 = (const float*)d_in[5];
    const float* W2 = (const float*)d_in[6];
    const float* b2 = (const float*)d_in[7];
    const float* g2 = (const float*)d_in[8];
    const float* be2 = (const float*)d_in[9];
    float* out = (float*)d_out;

    zero_kernel<<<(N_PTS + 255) / 256, 256>>>();
    count_kernel<<<(NK / 4 + 255) / 256, 256>>>((const int4*)idx);
    gemm1_kernel<<<(N_PTS + 127) / 128, 256>>>(feat, W1, b1);
    dim3 g2grid((N_PTS + 127) / 128, 2);
    gemm2_kernel<<<g2grid, 256>>>(W2, b2, g1, be1);
    gather_max_kernel<<<(N_PTS * 16 + 255) / 256, 256>>>(idx, g2, be2, out);
}

// round 12
// speedup vs baseline: 1.7802x; 1.0164x over previous
#include <cuda_runtime.h>
#include <cuda_fp16.h>
#include <cstdint>

#define N_PTS 100000
#define KNN   16
#define NK    (N_PTS * KNN)
#define EPSB  1e-5f
#define ASTRIDE 68   // padded A row stride (floats) -> conflict-free broadcasts

// ---------------- scratch (static device memory; no dynamic alloc) ----------
__device__ int    g_counts[N_PTS];
__device__ float  g_y1[(size_t)N_PTS * 64];    // pre-BN layer-1 output (fp32)
__device__ __half g_z[(size_t)N_PTS * 128];    // pre-BN layer-2 output (fp16)
__device__ float  g_stats1[2 * 64];            // weighted sum, sumsq
__device__ float  g_stats2[2 * 128];

// ---------------- packed f32x2 helpers --------------------------------------
__device__ __forceinline__ unsigned long long pack2s(float a) {
    unsigned long long r;
    asm("mov.b64 %0, {%1, %1};" : "=l"(r) : "f"(a));
    return r;
}
__device__ __forceinline__ float2 unpack2(unsigned long long v) {
    float2 r;
    asm("mov.b64 {%0, %1}, %2;" : "=f"(r.x), "=f"(r.y) : "l"(v));
    return r;
}
__device__ __forceinline__ void fma2(unsigned long long& d,
                                     unsigned long long a,
                                     unsigned long long b) {
    asm("fma.rn.f32x2 %0, %1, %2, %0;" : "+l"(d) : "l"(a), "l"(b));
}

// ---------------- small kernels ----------------------------------------------
__global__ void zero_kernel() {
    int i = blockIdx.x * blockDim.x + threadIdx.x;
    if (i < N_PTS) g_counts[i] = 0;
    if (i < 2 * 64) g_stats1[i] = 0.f;
    if (i < 2 * 128) g_stats2[i] = 0.f;
}

__global__ void count_kernel(const int4* __restrict__ idx4) {
    int i = blockIdx.x * blockDim.x + threadIdx.x;
    if (i < NK / 4) {
        int4 v = idx4[i];
        atomicAdd(&g_counts[v.x], 1);
        atomicAdd(&g_counts[v.y], 1);
        atomicAdd(&g_counts[v.z], 1);
        atomicAdd(&g_counts[v.w], 1);
    }
}

// GEMM1: y1 = feat @ W1 + b1 ; weighted BN1 stats.
// Block: 64 rows x 64 cols, 128 threads as 8(tx) x 16(ty); 6 CTAs/SM.
// Thread tile: 4 rows x 8 cols ({tx*4..+3, 32+tx*4..+3}).
__global__ __launch_bounds__(128, 6) void gemm1_kernel(const float* __restrict__ feat,
                                                       const float* __restrict__ W1,
                                                       const float* __restrict__ b1) {
    __shared__ float As[64 * ASTRIDE];   // ~17 KB, [row][k] padded
    __shared__ float Bs[64 * 64];        // 16 KB, [k][col]
    const int tid = threadIdx.x;
    const int tx = tid & 7, ty = tid >> 3;     // ty 0..15
    const int row0 = blockIdx.x * 64;

#pragma unroll
    for (int it = 0; it < 8; it++) {
        int f = tid + it * 128;
        ((float4*)Bs)[f] = ((const float4*)W1)[f];
    }
#pragma unroll
    for (int it = 0; it < 8; it++) {
        int f = tid + it * 128;          // [0, 1024)
        int r = f >> 4, k4 = f & 15;
        int grow = row0 + r;
        float4 v = (grow < N_PTS) ? ((const float4*)feat)[grow * 16 + k4]
                                  : make_float4(0.f, 0.f, 0.f, 0.f);
        *(float4*)&As[r * ASTRIDE + k4 * 4] = v;
    }
    __syncthreads();

    unsigned long long acc[4][4];
#pragma unroll
    for (int i = 0; i < 4; i++)
#pragma unroll
        for (int j = 0; j < 4; j++) acc[i][j] = 0ull;

#pragma unroll
    for (int kk = 0; kk < 64; kk += 2) {
        float2 a[4];
#pragma unroll
        for (int i = 0; i < 4; i++)
            a[i] = *(const float2*)&As[(ty * 4 + i) * ASTRIDE + kk];
#pragma unroll
        for (int kq = 0; kq < 2; kq++) {
            const ulonglong2 bA = *(const ulonglong2*)&Bs[(kk + kq) * 64 + tx * 4];
            const ulonglong2 bB = *(const ulonglong2*)&Bs[(kk + kq) * 64 + 32 + tx * 4];
#pragma unroll
            for (int i = 0; i < 4; i++) {
                unsigned long long ad = pack2s(kq ? a[i].y : a[i].x);
                fma2(acc[i][0], ad, bA.x);
                fma2(acc[i][1], ad, bA.y);
                fma2(acc[i][2], ad, bB.x);
                fma2(acc[i][3], ad, bB.y);
            }
        }
    }

    const float4 biasA = *(const float4*)&b1[tx * 4];
    const float4 biasB = *(const float4*)&b1[32 + tx * 4];
    float ws[8], wq[8];
#pragma unroll
    for (int j = 0; j < 8; j++) { ws[j] = 0.f; wq[j] = 0.f; }
#pragma unroll
    for (int i = 0; i < 4; i++) {
        int grow = row0 + ty * 4 + i;
        if (grow >= N_PTS) continue;
        float2 p0 = unpack2(acc[i][0]);
        float2 p1 = unpack2(acc[i][1]);
        float2 p2 = unpack2(acc[i][2]);
        float2 p3 = unpack2(acc[i][3]);
        float y[8];
        y[0] = p0.x + biasA.x; y[1] = p0.y + biasA.y;
        y[2] = p1.x + biasA.z; y[3] = p1.y + biasA.w;
        y[4] = p2.x + biasB.x; y[5] = p2.y + biasB.y;
        y[6] = p3.x + biasB.z; y[7] = p3.y + biasB.w;
        *(float4*)&g_y1[(size_t)grow * 64 + tx * 4] = make_float4(y[0], y[1], y[2], y[3]);
        *(float4*)&g_y1[(size_t)grow * 64 + 32 + tx * 4] = make_float4(y[4], y[5], y[6], y[7]);
        float w = (float)g_counts[grow];
#pragma unroll
        for (int j = 0; j < 8; j++) {
            ws[j] += w * y[j];
            wq[j] += w * y[j] * y[j];
        }
    }
    __syncthreads();
    float* red = As;  // 4352 floats available, need 2 * 2048... use 2*1024 per half
#pragma unroll
    for (int j = 0; j < 4; j++) {
        red[ty * 64 + tx * 4 + j] = ws[j];
        red[ty * 64 + 32 + tx * 4 + j] = ws[4 + j];
        red[1024 + ty * 64 + tx * 4 + j] = wq[j];
        red[1024 + ty * 64 + 32 + tx * 4 + j] = wq[4 + j];
    }
    __syncthreads();
    if (tid < 64) {
        float s = 0.f, q = 0.f;
#pragma unroll
        for (int t = 0; t < 16; t++) {
            s += red[t * 64 + tid];
            q += red[1024 + t * 64 + tid];
        }
        atomicAdd(&g_stats1[tid], s);
        atomicAdd(&g_stats1[64 + tid], q);
    }
}

// GEMM2: h = relu(bn1(y1)); y2 = h @ W2 + b2 -> fp16 g_z; weighted BN2 stats.
// Block: 64 rows x 64 cols (blockIdx.y = N-half), 128 threads as 16(tx) x 8(ty).
// Thread tile: 8 rows ({ty*4+i, 32+ty*4+i}) x 4 cols; 6 CTAs/SM.
__global__ __launch_bounds__(128, 6) void gemm2_kernel(const float* __restrict__ W2,
                                                       const float* __restrict__ b2,
                                                       const float* __restrict__ gamma1,
                                                       const float* __restrict__ beta1) {
    __shared__ float As[64 * ASTRIDE];   // ~17 KB, [row][k] padded
    __shared__ float Bs[64 * 64];        // 16 KB, [k][col-half]
    __shared__ float sb1s[128];
    const int tid = threadIdx.x;
    const int tx = tid & 15, ty = tid >> 4;    // ty 0..7
    const int row0 = blockIdx.x * 64;
    const int col0 = blockIdx.y * 64;

    if (tid < 64) {
        const float inv_m = 1.0f / (float)NK;
        float mean = g_stats1[tid] * inv_m;
        float var = g_stats1[64 + tid] * inv_m - mean * mean;
        float sc = gamma1[tid] * rsqrtf(var + EPSB);
        sb1s[tid] = sc;
        sb1s[64 + tid] = beta1[tid] - mean * sc;
    }
    // B half: Bs[k][0..63] = W2[k][col0..col0+63]
#pragma unroll
    for (int it = 0; it < 8; it++) {
        int f = tid + it * 128;           // [0, 1024): k = f>>4, c4 = f&15
        int k = f >> 4, c4 = f & 15;
        ((float4*)Bs)[f] = *(const float4*)&W2[k * 128 + col0 + c4 * 4];
    }
    __syncthreads();   // sb1s ready

#pragma unroll
    for (int it = 0; it < 8; it++) {
        int f = tid + it * 128;          // [0, 1024)
        int r = f >> 4, k4 = f & 15;
        int grow = row0 + r;
        float4 v = (grow < N_PTS) ? ((const float4*)g_y1)[grow * 16 + k4]
                                  : make_float4(0.f, 0.f, 0.f, 0.f);
        float4 s = *(const float4*)&sb1s[k4 * 4];
        float4 bb = *(const float4*)&sb1s[64 + k4 * 4];
        v.x = fmaxf(fmaf(v.x, s.x, bb.x), 0.f);
        v.y = fmaxf(fmaf(v.y, s.y, bb.y), 0.f);
        v.z = fmaxf(fmaf(v.z, s.z, bb.z), 0.f);
        v.w = fmaxf(fmaf(v.w, s.w, bb.w), 0.f);
        *(float4*)&As[r * ASTRIDE + k4 * 4] = v;
    }
    __syncthreads();

    unsigned long long acc[8][2];
#pragma unroll
    for (int i = 0; i < 8; i++) { acc[i][0] = 0ull; acc[i][1] = 0ull; }

#pragma unroll
    for (int kk = 0; kk < 64; kk += 2) {
        float2 a[8];
#pragma unroll
        for (int i = 0; i < 4; i++) {
            a[i]     = *(const float2*)&As[(ty * 4 + i) * ASTRIDE + kk];
            a[4 + i] = *(const float2*)&As[(32 + ty * 4 + i) * ASTRIDE + kk];
        }
#pragma unroll
        for (int kq = 0; kq < 2; kq++) {
            const ulonglong2 bA = *(const ulonglong2*)&Bs[(kk + kq) * 64 + tx * 4];
#pragma unroll
            for (int i = 0; i < 8; i++) {
                unsigned long long ad = pack2s(kq ? a[i].y : a[i].x);
                fma2(acc[i][0], ad, bA.x);
                fma2(acc[i][1], ad, bA.y);
            }
        }
    }

    const float4 biasA = *(const float4*)&b2[col0 + tx * 4];
    float ws[4] = {0.f, 0.f, 0.f, 0.f}, wq[4] = {0.f, 0.f, 0.f, 0.f};
#pragma unroll
    for (int i = 0; i < 8; i++) {
        int grow = row0 + ((i < 4) ? (ty * 4 + i) : (32 + ty * 4 + (i - 4)));
        if (grow >= N_PTS) continue;
        float2 p0 = unpack2(acc[i][0]);
        float2 p1 = unpack2(acc[i][1]);
        float y0 = p0.x + biasA.x, y1v = p0.y + biasA.y;
        float y2v = p1.x + biasA.z, y3 = p1.y + biasA.w;
        __half2 h0 = __floats2half2_rn(y0, y1v);
        __half2 h1 = __floats2half2_rn(y2v, y3);
        uint2 hv;
        hv.x = *(uint32_t*)&h0;
        hv.y = *(uint32_t*)&h1;
        *(uint2*)&g_z[(size_t)grow * 128 + col0 + tx * 4] = hv;
        float w = (float)g_counts[grow];
        ws[0] += w * y0;  wq[0] += w * y0 * y0;
        ws[1] += w * y1v; wq[1] += w * y1v * y1v;
        ws[2] += w * y2v; wq[2] += w * y2v * y2v;
        ws[3] += w * y3;  wq[3] += w * y3 * y3;
    }
    __syncthreads();
    float* red = As;  // need 2 * 512 floats
#pragma unroll
    for (int j = 0; j < 4; j++) {
        red[ty * 64 + tx * 4 + j] = ws[j];
        red[512 + ty * 64 + tx * 4 + j] = wq[j];
    }
    __syncthreads();
    if (tid < 64) {
        float s = 0.f, q = 0.f;
#pragma unroll
        for (int t = 0; t < 8; t++) {
            s += red[t * 64 + tid];
            q += red[512 + t * 64 + tid];
        }
        atomicAdd(&g_stats2[col0 + tid], s);
        atomicAdd(&g_stats2[128 + col0 + tid], q);
    }
}

// Final gather + max/min-pool over pre-BN fp16 table, then folded BN2
// affine + ReLU (per-thread from g_stats2). One warp = TWO points.
__global__ __launch_bounds__(256) void gather_max_kernel(
    const int* __restrict__ idx, const float* __restrict__ gamma2,
    const float* __restrict__ beta2, float* __restrict__ out) {
    int warp = (blockIdx.x * blockDim.x + threadIdx.x) >> 5;
    int lane = threadIdx.x & 31;
    int p = warp * 2 + (lane >> 4);
    if (p >= N_PTS) return;
    int half_lane = lane & 15;
    int c0 = half_lane * 8;

    int myidx = idx[p * 16 + half_lane];

    __half2 mx[4], mn[4];
#pragma unroll
    for (int j = 0; j < 4; j++) {
        mx[j] = __floats2half2_rn(-65504.f, -65504.f);
        mn[j] = __floats2half2_rn(65504.f, 65504.f);
    }

#pragma unroll
    for (int k = 0; k < 16; k++) {
        int r = __shfl_sync(0xffffffffu, myidx, (lane & 16) + k);
        uint4 raw = *(const uint4*)&g_z[(size_t)r * 128 + c0];
        __half2 v[4];
        *(uint4*)v = raw;
        mx[0] = __hmax2(mx[0], v[0]); mn[0] = __hmin2(mn[0], v[0]);
        mx[1] = __hmax2(mx[1], v[1]); mn[1] = __hmin2(mn[1], v[1]);
        mx[2] = __hmax2(mx[2], v[2]); mn[2] = __hmin2(mn[2], v[2]);
        mx[3] = __hmax2(mx[3], v[3]); mn[3] = __hmin2(mn[3], v[3]);
    }

    const float inv_m = 1.0f / (float)NK;
    float4 sum0 = *(const float4*)&g_stats2[c0];
    float4 sum1 = *(const float4*)&g_stats2[c0 + 4];
    float4 sq0 = *(const float4*)&g_stats2[128 + c0];
    float4 sq1 = *(const float4*)&g_stats2[128 + c0 + 4];
    float4 gm0 = *(const float4*)&gamma2[c0];
    float4 gm1 = *(const float4*)&gamma2[c0 + 4];
    float4 bt0 = *(const float4*)&beta2[c0];
    float4 bt1 = *(const float4*)&beta2[c0 + 4];
    float sm[8] = {sum0.x, sum0.y, sum0.z, sum0.w, sum1.x, sum1.y, sum1.z, sum1.w};
    float sq[8] = {sq0.x, sq0.y, sq0.z, sq0.w, sq1.x, sq1.y, sq1.z, sq1.w};
    float gm[8] = {gm0.x, gm0.y, gm0.z, gm0.w, gm1.x, gm1.y, gm1.z, gm1.w};
    float bt[8] = {bt0.x, bt0.y, bt0.z, bt0.w, bt1.x, bt1.y, bt1.z, bt1.w};

    float o[8];
#pragma unroll
    for (int j = 0; j < 8; j++) {
        float mean = sm[j] * inv_m;
        float var = sq[j] * inv_m - mean * mean;
        float sc = gm[j] * rsqrtf(var + EPSB);
        float bi = bt[j] - mean * sc;
        float2 fx = __half22float2(mx[j >> 1]);
        float2 fn = __half22float2(mn[j >> 1]);
        float vx = (j & 1) ? fx.y : fx.x;
        float vn = (j & 1) ? fn.y : fn.x;
        float m = (sc >= 0.f) ? vx : vn;
        o[j] = fmaxf(fmaf(sc, m, bi), 0.f);
    }
    size_t off = (size_t)p * 128 + c0;
    *(float4*)&out[off]     = make_float4(o[0], o[1], o[2], o[3]);
    *(float4*)&out[off + 4] = make_float4(o[4], o[5], o[6], o[7]);
}

// ---------------- launch ------------------------------------------------------
extern "C" void kernel_launch(void* const* d_in, const int* in_sizes, int n_in,
                              void* d_out, int out_size) {
    const float* feat = (const float*)d_in[0];
    const int* idx = (const int*)d_in[1];
    const float* W1 = (const float*)d_in[2];
    const float* b1 = (const float*)d_in[3];
    const float* g1 = (const float*)d_in[4];
    const float* be1 = (const float*)d_in[5];
    const float* W2 = (const float*)d_in[6];
    const float* b2 = (const float*)d_in[7];
    const float* g2 = (const float*)d_in[8];
    const float* be2 = (const float*)d_in[9];
    float* out = (float*)d_out;

    zero_kernel<<<(N_PTS + 255) / 256, 256>>>();
    count_kernel<<<(NK / 4 + 255) / 256, 256>>>((const int4*)idx);
    gemm1_kernel<<<(N_PTS + 63) / 64, 128>>>(feat, W1, b1);
    dim3 g2grid((N_PTS + 63) / 64, 2);
    gemm2_kernel<<<g2grid, 128>>>(W2, b2, g1, be1);
    gather_max_kernel<<<(N_PTS * 16 + 255) / 256, 256>>>(idx, g2, be2, out);
}